// round 2
// baseline (speedup 1.0000x reference)
#include <cuda_runtime.h>

#define NN 120000
#define DD 64
#define EE 2000000
#define SCAN_TILE 1024
#define NBLK ((NN + SCAN_TILE - 1) / SCAN_TILE)   // 118

// -------- scratch (static __device__ arrays; no allocations anywhere) --------
__device__ int   g_deg [NN];
__device__ float g_dis [NN];
__device__ int   g_off [NN + 1];
__device__ int   g_cur [NN];
__device__ int   g_esrc[EE];
__device__ float g_enorm[EE];
__device__ float g_embA[NN * DD];
__device__ float g_embB[NN * DD];
__device__ int   g_bsum[NBLK];

// ---------------------------------------------------------------- degree ----
__global__ void k_zero_deg() {
    int i = blockIdx.x * blockDim.x + threadIdx.x;
    if (i < NN) g_deg[i] = 0;
}

__global__ void k_count(const int* __restrict__ ei) {
    int e = blockIdx.x * blockDim.x + threadIdx.x;
    if (e < EE) atomicAdd(&g_deg[ei[EE + e]], 1);
}

// ------------------------------------------------------------ CSR offsets ---
__global__ void k_scan_reduce() {
    __shared__ int sh[256];
    int b = blockIdx.x, t = threadIdx.x;
    int base = b * SCAN_TILE;
    int sum = 0;
    for (int i = t; i < SCAN_TILE; i += 256) {
        int idx = base + i;
        if (idx < NN) sum += g_deg[idx];
    }
    sh[t] = sum; __syncthreads();
    for (int o = 128; o > 0; o >>= 1) {
        if (t < o) sh[t] += sh[t + o];
        __syncthreads();
    }
    if (t == 0) g_bsum[b] = sh[0];
}

__global__ void k_scan_top() {
    if (threadIdx.x == 0 && blockIdx.x == 0) {
        int run = 0;
        for (int i = 0; i < NBLK; i++) { int v = g_bsum[i]; g_bsum[i] = run; run += v; }
        g_off[NN] = run;   // == EE
    }
}

__global__ void k_scan_write() {
    __shared__ int sh[SCAN_TILE];
    int b = blockIdx.x, t = threadIdx.x;            // blockDim = 1024
    int idx = b * SCAN_TILE + t;
    int v = (idx < NN) ? g_deg[idx] : 0;
    sh[t] = v; __syncthreads();
    #pragma unroll
    for (int o = 1; o < SCAN_TILE; o <<= 1) {
        int x = (t >= o) ? sh[t - o] : 0;
        __syncthreads();
        sh[t] += x;
        __syncthreads();
    }
    if (idx < NN) {
        int excl = g_bsum[b] + sh[t] - v;           // exclusive prefix
        g_off[idx] = excl;
        g_cur[idx] = excl;
        g_dis[idx] = (v > 0) ? rsqrtf((float)v) : 0.0f;
    }
}

// --------------------------------------------------------------- bucketize --
__global__ void k_fill(const int* __restrict__ ei) {
    int e = blockIdx.x * blockDim.x + threadIdx.x;
    if (e >= EE) return;
    int s = ei[e];
    int d = ei[EE + e];
    int pos = atomicAdd(&g_cur[d], 1);
    g_esrc[pos]  = s;
    g_enorm[pos] = g_dis[s] * g_dis[d];
}

// ------------------------------------------------------------------- init ---
// g_embA = emb0 ; acc = emb0 ; optionally d_out[0:half] = emb0
__global__ void k_init(const float4* __restrict__ emb,
                       float4* __restrict__ out0,
                       float4* __restrict__ acc,
                       int write_emb0) {
    int i = blockIdx.x * blockDim.x + threadIdx.x;
    const int n4 = NN * DD / 4;
    if (i >= n4) return;
    float4 v = emb[i];
    ((float4*)g_embA)[i] = v;
    acc[i] = v;
    if (write_emb0) out0[i] = v;
}

// --------------------------------------------------------------- propagate --
// One warp per destination node. 32 lanes x float2 = one full 256B emb row.
// Pure gather (L2-resident table), coalesced writes, no float atomics.
__global__ void __launch_bounds__(256)
k_prop(const float* __restrict__ in, float* __restrict__ out,
       float* __restrict__ acc) {
    int warp = (blockIdx.x * blockDim.x + threadIdx.x) >> 5;
    int lane = threadIdx.x & 31;
    if (warp >= NN) return;

    int beg = g_off[warp];
    int end = g_off[warp + 1];

    const float2* __restrict__ in2 = (const float2*)in;
    float ax = 0.0f, ay = 0.0f;

    int e = beg;
    for (; e + 4 <= end; e += 4) {
        int   s0 = g_esrc[e + 0], s1 = g_esrc[e + 1];
        int   s2 = g_esrc[e + 2], s3 = g_esrc[e + 3];
        float w0 = g_enorm[e + 0], w1 = g_enorm[e + 1];
        float w2 = g_enorm[e + 2], w3 = g_enorm[e + 3];
        float2 x0 = __ldg(&in2[s0 * 32 + lane]);
        float2 x1 = __ldg(&in2[s1 * 32 + lane]);
        float2 x2 = __ldg(&in2[s2 * 32 + lane]);
        float2 x3 = __ldg(&in2[s3 * 32 + lane]);
        ax += w0 * x0.x; ay += w0 * x0.y;
        ax += w1 * x1.x; ay += w1 * x1.y;
        ax += w2 * x2.x; ay += w2 * x2.y;
        ax += w3 * x3.x; ay += w3 * x3.y;
    }
    for (; e < end; ++e) {
        int   s = g_esrc[e];
        float w = g_enorm[e];
        float2 x = __ldg(&in2[s * 32 + lane]);
        ax += w * x.x; ay += w * x.y;
    }

    int idx = warp * 32 + lane;
    ((float2*)out)[idx] = make_float2(ax, ay);
    float2 c = ((float2*)acc)[idx];
    c.x += ax; c.y += ay;
    ((float2*)acc)[idx] = c;
}

// -------------------------------------------------------------- final mean --
__global__ void k_scale(float4* __restrict__ acc) {
    int i = blockIdx.x * blockDim.x + threadIdx.x;
    const int n4 = NN * DD / 4;
    if (i >= n4) return;
    float4 v = acc[i];
    v.x *= 0.25f; v.y *= 0.25f; v.z *= 0.25f; v.w *= 0.25f;
    acc[i] = v;
}

// ---------------------------------------------------------------------------
extern "C" void kernel_launch(void* const* d_in, const int* in_sizes, int n_in,
                              void* d_out, int out_size) {
    const int*   ei  = (const int*)d_in[0];    // [2, E] int32 (src row, dst row)
    const float* emb = (const float*)d_in[1];  // [N, 64] float32
    (void)in_sizes; (void)n_in;

    const int half = NN * DD;
    float* out0;   // emb0 destination
    float* acc;    // running-mean destination
    if (out_size >= 2 * half) { out0 = (float*)d_out; acc = (float*)d_out + half; }
    else                      { out0 = nullptr;        acc = (float*)d_out; }
    int write_emb0 = (out0 != nullptr) ? 1 : 0;
    if (!write_emb0) out0 = acc;   // dummy, guarded by flag

    float* dA; cudaGetSymbolAddress((void**)&dA, g_embA);
    float* dB; cudaGetSymbolAddress((void**)&dB, g_embB);

    const int TE = 256;
    dim3 gN((NN + TE - 1) / TE);
    dim3 gE((EE + TE - 1) / TE);
    dim3 gI((NN * DD / 4 + TE - 1) / TE);
    dim3 gP((NN * 32 + TE - 1) / TE);          // one warp per node

    // ---- degree + CSR build (every call: deterministic amount of work) ----
    k_zero_deg   <<<gN, TE>>>();
    k_count      <<<gE, TE>>>(ei);
    k_scan_reduce<<<NBLK, 256>>>();
    k_scan_top   <<<1, 32>>>();
    k_scan_write <<<NBLK, SCAN_TILE>>>();
    k_fill       <<<gE, TE>>>(ei);

    // ---- init: embA = emb0, acc = emb0, d_out[0:half] = emb0 ----
    k_init<<<gI, TE>>>((const float4*)emb, (float4*)out0, (float4*)acc, write_emb0);

    // ---- 3 LightGCN propagation layers (ping-pong), acc += layer ----
    k_prop<<<gP, TE>>>(dA, dB, acc);
    k_prop<<<gP, TE>>>(dB, dA, acc);
    k_prop<<<gP, TE>>>(dA, dB, acc);

    // ---- out = acc / 4 ----
    k_scale<<<gI, TE>>>((float4*)acc);
}

// round 5
// speedup vs baseline: 1.3080x; 1.3080x over previous
#include <cuda_runtime.h>
#include <cuda_fp16.h>

#define NN 120000
#define DD 64
#define EE 2000000
#define SCAN_TILE 1024
#define NBLK ((NN + SCAN_TILE - 1) / SCAN_TILE)   // 118

// -------- scratch (static __device__ arrays; no allocations anywhere) --------
__device__ int    g_deg [NN];
__device__ float  g_dis [NN];
__device__ int    g_off [NN + 1];
__device__ int    g_cur [NN];
__device__ int2   g_emeta[EE];          // {src, __float_as_int(norm)}
__device__ __half g_h0[NN * DD];        // fp16 copies of layer embeddings
__device__ __half g_h1[NN * DD];
__device__ __half g_h2[NN * DD];
__device__ __half g_h3[NN * DD];
__device__ int    g_bsum[NBLK];

// ---------------------------------------------------------------- degree ----
__global__ void k_zero_deg() {
    int i = blockIdx.x * blockDim.x + threadIdx.x;
    if (i < NN) g_deg[i] = 0;
}

__global__ void k_count(const int* __restrict__ ei) {
    int e = blockIdx.x * blockDim.x + threadIdx.x;
    if (e < EE) atomicAdd(&g_deg[ei[EE + e]], 1);
}

// ------------------------------------------------------------ CSR offsets ---
__global__ void k_scan_reduce() {
    __shared__ int sh[256];
    int b = blockIdx.x, t = threadIdx.x;
    int base = b * SCAN_TILE;
    int sum = 0;
    for (int i = t; i < SCAN_TILE; i += 256) {
        int idx = base + i;
        if (idx < NN) sum += g_deg[idx];
    }
    sh[t] = sum; __syncthreads();
    for (int o = 128; o > 0; o >>= 1) {
        if (t < o) sh[t] += sh[t + o];
        __syncthreads();
    }
    if (t == 0) g_bsum[b] = sh[0];
}

// parallel exclusive scan over the NBLK (=118) block sums, one block
__global__ void k_scan_top() {
    __shared__ int sh[128];
    int t = threadIdx.x;
    int v = (t < NBLK) ? g_bsum[t] : 0;
    sh[t] = v; __syncthreads();
    #pragma unroll
    for (int o = 1; o < 128; o <<= 1) {
        int x = (t >= o) ? sh[t - o] : 0;
        __syncthreads();
        sh[t] += x;
        __syncthreads();
    }
    if (t < NBLK) g_bsum[t] = sh[t] - v;           // exclusive
    if (t == 0)   g_off[NN] = sh[127];             // == EE
}

__global__ void k_scan_write() {
    __shared__ int sh[SCAN_TILE];
    int b = blockIdx.x, t = threadIdx.x;            // blockDim = 1024
    int idx = b * SCAN_TILE + t;
    int v = (idx < NN) ? g_deg[idx] : 0;
    sh[t] = v; __syncthreads();
    #pragma unroll
    for (int o = 1; o < SCAN_TILE; o <<= 1) {
        int x = (t >= o) ? sh[t - o] : 0;
        __syncthreads();
        sh[t] += x;
        __syncthreads();
    }
    if (idx < NN) {
        int excl = g_bsum[b] + sh[t] - v;           // exclusive prefix
        g_off[idx] = excl;
        g_cur[idx] = excl;
        g_dis[idx] = (v > 0) ? rsqrtf((float)v) : 0.0f;
    }
}

// --------------------------------------------------------------- bucketize --
__global__ void k_fill(const int* __restrict__ ei) {
    int e = blockIdx.x * blockDim.x + threadIdx.x;
    if (e >= EE) return;
    int s = ei[e];
    int d = ei[EE + e];
    int pos = atomicAdd(&g_cur[d], 1);
    g_emeta[pos] = make_int2(s, __float_as_int(g_dis[s] * g_dis[d]));
}

// ------------------------------------------------------------------- init ---
// out0 = emb0 (fp32), g_h0 = fp16(emb0)
__global__ void k_init(const float4* __restrict__ emb,
                       float4* __restrict__ out0,
                       int write_emb0) {
    int i = blockIdx.x * blockDim.x + threadIdx.x;
    const int n4 = NN * DD / 4;
    if (i >= n4) return;
    float4 v = emb[i];
    if (write_emb0) out0[i] = v;
    __half2 h[2];
    h[0] = __floats2half2_rn(v.x, v.y);
    h[1] = __floats2half2_rn(v.z, v.w);
    ((uint2*)g_h0)[i] = *(uint2*)h;
}

// --------------------------------------------------------------- propagate --
// One warp per destination node. 32 lanes x half2 = one full 128B fp16 row.
// Pure gather (fp16 table, L2-resident), fp32 accumulation, coalesced write.
__global__ void __launch_bounds__(256)
k_prop(const __half2* __restrict__ in, __half2* __restrict__ out) {
    int warp = (blockIdx.x * blockDim.x + threadIdx.x) >> 5;
    int lane = threadIdx.x & 31;
    if (warp >= NN) return;

    int beg = g_off[warp];
    int end = g_off[warp + 1];

    float ax = 0.0f, ay = 0.0f;

    int e = beg;
    for (; e + 8 <= end; e += 8) {
        int2 m0 = g_emeta[e + 0], m1 = g_emeta[e + 1];
        int2 m2 = g_emeta[e + 2], m3 = g_emeta[e + 3];
        int2 m4 = g_emeta[e + 4], m5 = g_emeta[e + 5];
        int2 m6 = g_emeta[e + 6], m7 = g_emeta[e + 7];
        __half2 v0 = __ldg(&in[m0.x * 32 + lane]);
        __half2 v1 = __ldg(&in[m1.x * 32 + lane]);
        __half2 v2 = __ldg(&in[m2.x * 32 + lane]);
        __half2 v3 = __ldg(&in[m3.x * 32 + lane]);
        __half2 v4 = __ldg(&in[m4.x * 32 + lane]);
        __half2 v5 = __ldg(&in[m5.x * 32 + lane]);
        __half2 v6 = __ldg(&in[m6.x * 32 + lane]);
        __half2 v7 = __ldg(&in[m7.x * 32 + lane]);
        float2 f;
        f = __half22float2(v0); ax += __int_as_float(m0.y) * f.x; ay += __int_as_float(m0.y) * f.y;
        f = __half22float2(v1); ax += __int_as_float(m1.y) * f.x; ay += __int_as_float(m1.y) * f.y;
        f = __half22float2(v2); ax += __int_as_float(m2.y) * f.x; ay += __int_as_float(m2.y) * f.y;
        f = __half22float2(v3); ax += __int_as_float(m3.y) * f.x; ay += __int_as_float(m3.y) * f.y;
        f = __half22float2(v4); ax += __int_as_float(m4.y) * f.x; ay += __int_as_float(m4.y) * f.y;
        f = __half22float2(v5); ax += __int_as_float(m5.y) * f.x; ay += __int_as_float(m5.y) * f.y;
        f = __half22float2(v6); ax += __int_as_float(m6.y) * f.x; ay += __int_as_float(m6.y) * f.y;
        f = __half22float2(v7); ax += __int_as_float(m7.y) * f.x; ay += __int_as_float(m7.y) * f.y;
    }
    for (; e < end; ++e) {
        int2 m = g_emeta[e];
        __half2 v = __ldg(&in[m.x * 32 + lane]);
        float2 f = __half22float2(v);
        float w = __int_as_float(m.y);
        ax += w * f.x; ay += w * f.y;
    }

    out[warp * 32 + lane] = __floats2half2_rn(ax, ay);
}

// --------------------------------------------- final mean: (e0+h1+h2+h3)/4 --
__global__ void k_final(const float2* __restrict__ emb,
                        float2* __restrict__ out) {
    int i = blockIdx.x * blockDim.x + threadIdx.x;
    const int n2 = NN * DD / 2;
    if (i >= n2) return;
    float2 e  = emb[i];
    float2 a = __half22float2(((const __half2*)g_h1)[i]);
    float2 b = __half22float2(((const __half2*)g_h2)[i]);
    float2 c = __half22float2(((const __half2*)g_h3)[i]);
    out[i] = make_float2((e.x + a.x + b.x + c.x) * 0.25f,
                         (e.y + a.y + b.y + c.y) * 0.25f);
}

// ---------------------------------------------------------------------------
extern "C" void kernel_launch(void* const* d_in, const int* in_sizes, int n_in,
                              void* d_out, int out_size) {
    const int*   ei  = (const int*)d_in[0];    // [2, E] int32 (src row, dst row)
    const float* emb = (const float*)d_in[1];  // [N, 64] float32
    (void)in_sizes; (void)n_in;

    const int half = NN * DD;
    float* out0;   // emb0 destination
    float* outp;   // mean destination
    if (out_size >= 2 * half) { out0 = (float*)d_out; outp = (float*)d_out + half; }
    else                      { out0 = nullptr;        outp = (float*)d_out; }
    int write_emb0 = (out0 != nullptr) ? 1 : 0;
    if (!write_emb0) out0 = outp;   // dummy, guarded by flag

    __half2* h0; cudaGetSymbolAddress((void**)&h0, g_h0);
    __half2* h1; cudaGetSymbolAddress((void**)&h1, g_h1);
    __half2* h2; cudaGetSymbolAddress((void**)&h2, g_h2);
    __half2* h3; cudaGetSymbolAddress((void**)&h3, g_h3);

    const int TE = 256;
    dim3 gN((NN + TE - 1) / TE);
    dim3 gE((EE + TE - 1) / TE);
    dim3 gI((NN * DD / 4 + TE - 1) / TE);
    dim3 gF((NN * DD / 2 + TE - 1) / TE);
    dim3 gP((NN * 32 + TE - 1) / TE);          // one warp per node

    // ---- degree + CSR build ----
    k_zero_deg   <<<gN, TE>>>();
    k_count      <<<gE, TE>>>(ei);
    k_scan_reduce<<<NBLK, 256>>>();
    k_scan_top   <<<1, 128>>>();
    k_scan_write <<<NBLK, SCAN_TILE>>>();
    k_fill       <<<gE, TE>>>(ei);

    // ---- init: h0 = fp16(emb0), d_out[0:half] = emb0 ----
    k_init<<<gI, TE>>>((const float4*)emb, (float4*)out0, write_emb0);

    // ---- 3 LightGCN propagation layers (fp16 table, fp32 accumulate) ----
    k_prop<<<gP, TE>>>(h0, h1);
    k_prop<<<gP, TE>>>(h1, h2);
    k_prop<<<gP, TE>>>(h2, h3);

    // ---- out = (emb0 + h1 + h2 + h3) / 4 ----
    k_final<<<gF, TE>>>((const float2*)emb, (float2*)outp);
}